// round 9
// baseline (speedup 1.0000x reference)
#include <cuda_runtime.h>
#include <cuda_fp16.h>

#define Bn 2
#define Vn 5
#define Cn 32
#define Hn 256
#define Wn 320
#define Dn 4
#define HWn (Hn*Wn)
#define VAR_ELEMS (Bn*Cn*Dn*HWn)  // 20971520

// rot(9) + trans(3) per (b, v) for v=1..Vn-1
__device__ float g_rt[Bn*Vn*12];
// feats transposed to [B, V, H*W, C] in fp16 (channel-contiguous 64B pixel lines)
__device__ __half2 g_fT[(size_t)Bn*Vn*HWn*(Cn/2)];

// ---------------------------------------------------------------------------
// f32x2 packed-math helpers (Blackwell-only PTX; ptxas won't auto-emit these)
// ---------------------------------------------------------------------------
__device__ __forceinline__ unsigned long long pk2(float a, float b) {
    unsigned long long r;
    asm("mov.b64 %0, {%1, %2};" : "=l"(r) : "f"(a), "f"(b));
    return r;
}
__device__ __forceinline__ float2 upk2(unsigned long long v) {
    float2 r;
    asm("mov.b64 {%0, %1}, %2;" : "=f"(r.x), "=f"(r.y) : "l"(v));
    return r;
}
__device__ __forceinline__ unsigned long long mul2(unsigned long long a, unsigned long long b) {
    unsigned long long r;
    asm("mul.rn.f32x2 %0, %1, %2;" : "=l"(r) : "l"(a), "l"(b));
    return r;
}
__device__ __forceinline__ unsigned long long fma2(unsigned long long a, unsigned long long b,
                                                   unsigned long long c) {
    unsigned long long r;
    asm("fma.rn.f32x2 %0, %1, %2, %3;" : "=l"(r) : "l"(a), "l"(b), "l"(c));
    return r;
}
__device__ __forceinline__ void acc2(unsigned long long& s, unsigned long long& q, float2 v) {
    unsigned long long pv = pk2(v.x, v.y);
    asm("add.rn.f32x2 %0, %0, %1;" : "+l"(s) : "l"(pv));
    asm("fma.rn.f32x2 %0, %1, %1, %0;" : "+l"(q) : "l"(pv));
}

// ---------------------------------------------------------------------------
// Prep (device-side, lane-parallel): combine projections, structured inverse
// ---------------------------------------------------------------------------
__device__ __forceinline__ void combine_f32(const float* p, float M[4][4]) {
    const float* E = p;
    const float* K = p + 16;
    #pragma unroll
    for (int i = 0; i < 4; i++)
        #pragma unroll
        for (int j = 0; j < 4; j++)
            M[i][j] = E[i*4 + j];
    #pragma unroll
    for (int i = 0; i < 3; i++)
        #pragma unroll
        for (int j = 0; j < 4; j++) {
            float s = 0.f;
            #pragma unroll
            for (int k = 0; k < 3; k++) s += K[i*4 + k] * E[k*4 + j];
            M[i][j] = s;
        }
}

__device__ void prep_lane(const float* __restrict__ proj, int l) {
    const int b = l / (Vn - 1);
    const int v = (l % (Vn - 1)) + 1;

    float Pr[4][4];
    combine_f32(proj + (size_t)(b*Vn + 0) * 32, Pr);

    double m00 = Pr[0][0], m01 = Pr[0][1], m02 = Pr[0][2];
    double m10 = Pr[1][0], m11 = Pr[1][1], m12 = Pr[1][2];
    double m20 = Pr[2][0], m21 = Pr[2][1], m22 = Pr[2][2];
    double t0  = Pr[0][3], t1  = Pr[1][3], t2  = Pr[2][3];

    double c00 = m11*m22 - m12*m21;
    double c01 = m12*m20 - m10*m22;
    double c02 = m10*m21 - m11*m20;
    double det = m00*c00 + m01*c01 + m02*c02;
    double id  = 1.0 / det;

    double inv3[3][3];
    inv3[0][0] = c00*id; inv3[0][1] = (m02*m21 - m01*m22)*id; inv3[0][2] = (m01*m12 - m02*m11)*id;
    inv3[1][0] = c01*id; inv3[1][1] = (m00*m22 - m02*m20)*id; inv3[1][2] = (m02*m10 - m00*m12)*id;
    inv3[2][0] = c02*id; inv3[2][1] = (m01*m20 - m00*m21)*id; inv3[2][2] = (m00*m11 - m01*m10)*id;

    double it[3];
    #pragma unroll
    for (int k = 0; k < 3; k++)
        it[k] = -(inv3[k][0]*t0 + inv3[k][1]*t1 + inv3[k][2]*t2);

    float Ps[4][4];
    combine_f32(proj + (size_t)(b*Vn + v) * 32, Ps);
    float* o = g_rt + (b*Vn + v) * 12;
    #pragma unroll
    for (int i = 0; i < 3; i++) {
        double r0 = 0, r1 = 0, r2 = 0, t = (double)Ps[i][3];
        #pragma unroll
        for (int k = 0; k < 3; k++) {
            double s = (double)Ps[i][k];
            r0 += s * inv3[k][0];
            r1 += s * inv3[k][1];
            r2 += s * inv3[k][2];
            t  += s * it[k];
        }
        o[i*3 + 0] = (float)r0;
        o[i*3 + 1] = (float)r1;
        o[i*3 + 2] = (float)r2;
        o[9 + i]   = (float)t;
    }
}

// ---------------------------------------------------------------------------
// Transpose+convert: feats [BV, C, HW] f32 -> g_fT [BV, HW, C] fp16.
// Block (0,0) additionally runs prep on lanes 0..7 (hidden under transpose).
// ---------------------------------------------------------------------------
__global__ void __launch_bounds__(256)
transpose_kernel(const float* __restrict__ feats, const float* __restrict__ proj) {
    __shared__ float tile[32][65];
    const int bv   = blockIdx.y;
    const int pix0 = blockIdx.x * 64;
    const int tid = threadIdx.x;
    const int tx = tid & 15;
    const int ty = tid >> 4;

    const float* src = feats + (size_t)bv * (Cn*HWn);
    #pragma unroll
    for (int r = 0; r < 2; r++) {
        int ch = ty + 16*r;
        float4 v = *(const float4*)(src + (size_t)ch*HWn + pix0 + tx*4);
        tile[ch][tx*4 + 0] = v.x;
        tile[ch][tx*4 + 1] = v.y;
        tile[ch][tx*4 + 2] = v.z;
        tile[ch][tx*4 + 3] = v.w;
    }
    __syncthreads();

    const int p = tid >> 2;
    const int q = tid & 3;
    __half2 h[4];
    #pragma unroll
    for (int k = 0; k < 4; k++) {
        int c = q*8 + 2*k;
        h[k] = __floats2half2_rn(tile[c][p], tile[c+1][p]);
    }
    uint4 pkv = make_uint4(*(unsigned*)&h[0], *(unsigned*)&h[1],
                           *(unsigned*)&h[2], *(unsigned*)&h[3]);
    uint4* dst = (uint4*)(g_fT + ((size_t)bv*HWn + pix0) * 16);
    dst[p*4 + q] = pkv;

    if (blockIdx.x == 0 && blockIdx.y == 0 && tid < Bn*(Vn-1))
        prep_lane(proj, tid);
}

// ---------------------------------------------------------------------------
// Main kernel: thread = (b, pixel, cc); cc owns channels [cc*8, cc*8+8).
// Lane-split coords + packed width-4 shuffle exchange; f32x2 accumulation.
// Variance staged in smem -> fully coalesced 128B global stores.
// ---------------------------------------------------------------------------
__global__ void __launch_bounds__(256, 4)
hammer_kernel(const float* __restrict__ depthv,
              float* __restrict__ outv,
              float* __restrict__ outm)
{
    __shared__ float s_rt[Bn*Vn*12];
    __shared__ float s_out[32*65];   // [channel][pixel-in-block], pitch 65

    const int t = threadIdx.x;
    if (t < Bn*Vn*12) s_rt[t] = g_rt[t];
    __syncthreads();

    const int cc   = t & 3;
    const int pl   = t >> 2;              // 0..63 pixel-in-block
    const int lane = t & 31;
    const int w    = t >> 5;
    const int pg   = blockIdx.x*64 + pl;  // global (b,pixel) index
    const int b    = pg / HWn;
    const int pix  = pg - b*HWn;
    const int pixbase = blockIdx.x*64 - b*HWn;  // pix of pl==0 (b uniform per block)
    const float xf = (float)(pix % Wn);
    const float yf = (float)(pix / Wn);

    // depth for all 4 planes up front
    float dep4[Dn];
    #pragma unroll
    for (int d = 0; d < Dn; d++)
        dep4[d] = __ldg(depthv + (b*Dn + d)*HWn + pix);

    // reference view (d-invariant): packed f32x2 values only
    unsigned long long rvs[4];
    {
        uint4 ru = __ldg((const uint4*)(g_fT + ((size_t)(b*Vn)*HWn + pix)*16 + cc*4));
        const __half2* hp = (const __half2*)&ru;
        #pragma unroll
        for (int k = 0; k < 4; k++) {
            float2 a = __half22float2(hp[k]);
            rvs[k] = pk2(a.x, a.y);
        }
    }

    // this lane's view (vi = cc): row dots + translation, hoisted
    const float* M = &s_rt[(b*Vn + cc + 1)*12];
    const float Ar = fmaf(M[0], xf, fmaf(M[1], yf, M[2]));
    const float Br = fmaf(M[3], xf, fmaf(M[4], yf, M[5]));
    const float Cr = fmaf(M[6], xf, fmaf(M[7], yf, M[8]));
    const float T9 = M[9], T10 = M[10], T11 = M[11];
    const int   vline_mine = (b*Vn + cc + 1)*HWn;  // pixel-line base index (<2^20)

    const unsigned long long C02 = pk2( 0.2f,  0.2f);
    const unsigned long long CN2 = pk2(-0.2f, -0.2f);

    unsigned vbits = 0;

    #pragma unroll 1
    for (int d = 0; d < Dn; d++) {
        const float dep = dep4[d];

        // ---- my view's warp params ----
        float pxv = fmaf(Ar, dep, T9);
        float pyv = fmaf(Br, dep, T10);
        float pzv = fmaf(Cr, dep, T11);
        float rz = __frcp_rn(pzv);
        float gx = pxv * rz;
        float gy = pyv * rz;

        float fx0 = floorf(gx), fy0 = floorf(gy);
        float ax = gx - fx0,    ay = gy - fy0;
        int x0 = (int)fx0, y0 = (int)fy0;
        int x1 = x0 + 1,   y1 = y0 + 1;
        float wx0 = (x0 >= 0 && x0 < Wn) ? (1.f - ax) : 0.f;
        float wx1 = (x1 >= 0 && x1 < Wn) ? ax : 0.f;
        float wy0 = (y0 >= 0 && y0 < Hn) ? (1.f - ay) : 0.f;
        float wy1 = (y1 >= 0 && y1 < Hn) ? ay : 0.f;

        if (((wx0 + wx1) * (wy0 + wy1)) != 0.f) vbits |= (1u << d);

        int pb = min(max(x0, 0), Wn - 2);
        float wxA = (x0 == pb)     ? wx0 : ((x1 == pb)     ? wx1 : 0.f);
        float wxB = (x1 == pb + 1) ? wx1 : ((x0 == pb + 1) ? wx0 : 0.f);
        int y0c = min(max(y0, 0), Hn - 1);
        int y1c = min(max(y1, 0), Hn - 1);

        __half2 wxh = __floats2half2_rn(wxA, wxB);
        __half2 wyh = __floats2half2_rn(wy0, wy1);
        unsigned wxu = *(unsigned*)&wxh;
        unsigned wyu = *(unsigned*)&wyh;
        // pack both row offsets: 20-bit pixel-line index + 1-bit (y1c-y0c)
        int pko = (vline_mine + y0c*Wn + pb) | ((y1c - y0c) << 20);

        unsigned long long s2[4], q2[4];
        #pragma unroll
        for (int k = 0; k < 4; k++) {
            s2[k] = rvs[k];
            q2[k] = mul2(rvs[k], rvs[k]);
        }

        #pragma unroll
        for (int vi = 0; vi < 4; vi++) {
            int pv       = __shfl_sync(0xffffffffu, pko, vi, 4);
            unsigned wxb = __shfl_sync(0xffffffffu, wxu, vi, 4);
            unsigned wyb = __shfl_sync(0xffffffffu, wyu, vi, 4);
            int l0 = pv & 0xFFFFF;
            int l1 = l0 + ((pv >> 20) ? Wn : 0);
            __half2 wxv = *(__half2*)&wxb;
            __half2 wyv = *(__half2*)&wyb;
            __half2 wxA2 = __half2half2(__low2half(wxv));
            __half2 wxB2 = __half2half2(__high2half(wxv));
            __half2 wy02 = __half2half2(__low2half(wyv));
            __half2 wy12 = __half2half2(__high2half(wyv));

            const __half2* r0 = g_fT + (size_t)l0*16 + cc*4;
            const __half2* r1 = g_fT + (size_t)l1*16 + cc*4;
            uint4 u00 = __ldg((const uint4*)r0);
            uint4 u01 = __ldg((const uint4*)(r0 + 16));
            uint4 u10 = __ldg((const uint4*)r1);
            uint4 u11 = __ldg((const uint4*)(r1 + 16));

            const __half2* h00 = (const __half2*)&u00;
            const __half2* h01 = (const __half2*)&u01;
            const __half2* h10 = (const __half2*)&u10;
            const __half2* h11 = (const __half2*)&u11;

            #pragma unroll
            for (int k = 0; k < 4; k++) {
                __half2 ra = __hfma2(wxB2, h01[k], __hmul2(wxA2, h00[k]));
                __half2 rb = __hfma2(wxB2, h11[k], __hmul2(wxA2, h10[k]));
                __half2 v2 = __hfma2(wy12, rb, __hmul2(wy02, ra));
                acc2(s2[k], q2[k], __half22float2(v2));
            }
        }

        // ---- stage variance to smem (conflict-free) ----
        #pragma unroll
        for (int k = 0; k < 4; k++) {
            unsigned long long u  = mul2(s2[k], C02);
            unsigned long long un = mul2(s2[k], CN2);
            unsigned long long qc = mul2(q2[k], C02);
            float2 r = upk2(fma2(u, un, qc));
            s_out[(cc*8 + 2*k)    *65 + pl] = r.x;
            s_out[(cc*8 + 2*k + 1)*65 + pl] = r.y;
        }
        __syncthreads();

        // ---- coalesced 128B store phase: warp w writes 8 (channel,half) slots ----
        #pragma unroll
        for (int s = 0; s < 8; s++) {
            int idx = w*8 + s;        // 0..63
            int c  = idx >> 1;
            int ph = idx & 1;
            outv[((b*Cn + c)*Dn + d)*HWn + pixbase + ph*32 + lane] =
                s_out[c*65 + ph*32 + lane];
        }
        __syncthreads();
    }

    // mask: popcount own-view bits, sum across the 4 views of this pixel
    int ms = __popc(vbits);
    ms += __shfl_xor_sync(0xffffffffu, ms, 1, 4);
    ms += __shfl_xor_sync(0xffffffffu, ms, 2, 4);
    if (cc == 0) outm[b*HWn + pix] = (float)ms;
}

// ---------------------------------------------------------------------------
// Launch
// ---------------------------------------------------------------------------
extern "C" void kernel_launch(void* const* d_in, const int* in_sizes, int n_in,
                              void* d_out, int out_size)
{
    const float* feats  = (const float*)d_in[0];
    const float* proj   = (const float*)d_in[1];
    const float* depthv = (const float*)d_in[2];

    float* outv = (float*)d_out;
    float* outm = outv + VAR_ELEMS;

    transpose_kernel<<<dim3(HWn/64, Bn*Vn), 256>>>(feats, proj);
    hammer_kernel<<<(Bn*HWn*4)/256, 256>>>(depthv, outv, outm);
}

// round 10
// speedup vs baseline: 1.1655x; 1.1655x over previous
#include <cuda_runtime.h>
#include <cuda_fp16.h>

#define Bn 2
#define Vn 5
#define Cn 32
#define Hn 256
#define Wn 320
#define Dn 4
#define HWn (Hn*Wn)
#define VAR_ELEMS (Bn*Cn*Dn*HWn)  // 20971520

// rot(9) + trans(3) per (b, v) for v=1..Vn-1
__device__ float g_rt[Bn*Vn*12];
// src views 1..4 transposed to [B, 4, H*W, C] fp16 (channel-contiguous 64B lines)
__device__ __half2 g_fT[(size_t)Bn*4*HWn*(Cn/2)];

// ---------------------------------------------------------------------------
// f32x2 packed-math helpers (Blackwell-only PTX; ptxas won't auto-emit these)
// ---------------------------------------------------------------------------
__device__ __forceinline__ unsigned long long pk2(float a, float b) {
    unsigned long long r;
    asm("mov.b64 %0, {%1, %2};" : "=l"(r) : "f"(a), "f"(b));
    return r;
}
__device__ __forceinline__ float2 upk2(unsigned long long v) {
    float2 r;
    asm("mov.b64 {%0, %1}, %2;" : "=f"(r.x), "=f"(r.y) : "l"(v));
    return r;
}
__device__ __forceinline__ unsigned long long mul2(unsigned long long a, unsigned long long b) {
    unsigned long long r;
    asm("mul.rn.f32x2 %0, %1, %2;" : "=l"(r) : "l"(a), "l"(b));
    return r;
}
__device__ __forceinline__ unsigned long long fma2(unsigned long long a, unsigned long long b,
                                                   unsigned long long c) {
    unsigned long long r;
    asm("fma.rn.f32x2 %0, %1, %2, %3;" : "=l"(r) : "l"(a), "l"(b), "l"(c));
    return r;
}
__device__ __forceinline__ void acc2(unsigned long long& s, unsigned long long& q, float2 v) {
    unsigned long long pv = pk2(v.x, v.y);
    asm("add.rn.f32x2 %0, %0, %1;" : "+l"(s) : "l"(pv));
    asm("fma.rn.f32x2 %0, %1, %1, %0;" : "+l"(q) : "l"(pv));
}

// ---------------------------------------------------------------------------
// Prep (device-side, lane-parallel): combine projections, structured inverse
// ---------------------------------------------------------------------------
__device__ __forceinline__ void combine_f32(const float* p, float M[4][4]) {
    const float* E = p;
    const float* K = p + 16;
    #pragma unroll
    for (int i = 0; i < 4; i++)
        #pragma unroll
        for (int j = 0; j < 4; j++)
            M[i][j] = E[i*4 + j];
    #pragma unroll
    for (int i = 0; i < 3; i++)
        #pragma unroll
        for (int j = 0; j < 4; j++) {
            float s = 0.f;
            #pragma unroll
            for (int k = 0; k < 3; k++) s += K[i*4 + k] * E[k*4 + j];
            M[i][j] = s;
        }
}

__device__ void prep_lane(const float* __restrict__ proj, int l) {
    const int b = l / (Vn - 1);
    const int v = (l % (Vn - 1)) + 1;

    float Pr[4][4];
    combine_f32(proj + (size_t)(b*Vn + 0) * 32, Pr);

    double m00 = Pr[0][0], m01 = Pr[0][1], m02 = Pr[0][2];
    double m10 = Pr[1][0], m11 = Pr[1][1], m12 = Pr[1][2];
    double m20 = Pr[2][0], m21 = Pr[2][1], m22 = Pr[2][2];
    double t0  = Pr[0][3], t1  = Pr[1][3], t2  = Pr[2][3];

    double c00 = m11*m22 - m12*m21;
    double c01 = m12*m20 - m10*m22;
    double c02 = m10*m21 - m11*m20;
    double det = m00*c00 + m01*c01 + m02*c02;
    double id  = 1.0 / det;

    double inv3[3][3];
    inv3[0][0] = c00*id; inv3[0][1] = (m02*m21 - m01*m22)*id; inv3[0][2] = (m01*m12 - m02*m11)*id;
    inv3[1][0] = c01*id; inv3[1][1] = (m00*m22 - m02*m20)*id; inv3[1][2] = (m02*m10 - m00*m12)*id;
    inv3[2][0] = c02*id; inv3[2][1] = (m01*m20 - m00*m21)*id; inv3[2][2] = (m00*m11 - m01*m10)*id;

    double it[3];
    #pragma unroll
    for (int k = 0; k < 3; k++)
        it[k] = -(inv3[k][0]*t0 + inv3[k][1]*t1 + inv3[k][2]*t2);

    float Ps[4][4];
    combine_f32(proj + (size_t)(b*Vn + v) * 32, Ps);
    float* o = g_rt + (b*Vn + v) * 12;
    #pragma unroll
    for (int i = 0; i < 3; i++) {
        double r0 = 0, r1 = 0, r2 = 0, t = (double)Ps[i][3];
        #pragma unroll
        for (int k = 0; k < 3; k++) {
            double s = (double)Ps[i][k];
            r0 += s * inv3[k][0];
            r1 += s * inv3[k][1];
            r2 += s * inv3[k][2];
            t  += s * it[k];
        }
        o[i*3 + 0] = (float)r0;
        o[i*3 + 1] = (float)r1;
        o[i*3 + 2] = (float)r2;
        o[9 + i]   = (float)t;
    }
}

// ---------------------------------------------------------------------------
// Transpose+convert (views 1..4 only): feats [b,v,C,HW] f32 -> g_fT fp16.
// Block (0,0) additionally runs prep on lanes 0..7 (hidden under transpose).
// ---------------------------------------------------------------------------
__global__ void __launch_bounds__(256)
transpose_kernel(const float* __restrict__ feats, const float* __restrict__ proj) {
    __shared__ float tile[32][65];
    const int bv   = blockIdx.y;          // 0..Bn*4-1
    const int b    = bv >> 2;
    const int v    = (bv & 3) + 1;
    const int pix0 = blockIdx.x * 64;
    const int tid = threadIdx.x;
    const int tx = tid & 15;
    const int ty = tid >> 4;

    const float* src = feats + (size_t)(b*Vn + v) * (Cn*HWn);
    #pragma unroll
    for (int r = 0; r < 2; r++) {
        int ch = ty + 16*r;
        float4 vv = *(const float4*)(src + (size_t)ch*HWn + pix0 + tx*4);
        tile[ch][tx*4 + 0] = vv.x;
        tile[ch][tx*4 + 1] = vv.y;
        tile[ch][tx*4 + 2] = vv.z;
        tile[ch][tx*4 + 3] = vv.w;
    }
    __syncthreads();

    const int p = tid >> 2;
    const int q = tid & 3;
    __half2 h[4];
    #pragma unroll
    for (int k = 0; k < 4; k++) {
        int c = q*8 + 2*k;
        h[k] = __floats2half2_rn(tile[c][p], tile[c+1][p]);
    }
    uint4 pkv = make_uint4(*(unsigned*)&h[0], *(unsigned*)&h[1],
                           *(unsigned*)&h[2], *(unsigned*)&h[3]);
    uint4* dst = (uint4*)(g_fT + ((size_t)bv*HWn + pix0) * 16);
    dst[p*4 + q] = pkv;

    if (blockIdx.x == 0 && blockIdx.y == 0 && tid < Bn*(Vn-1))
        prep_lane(proj, tid);
}

// ---------------------------------------------------------------------------
// Main kernel: thread = (b, pixel, cc); cc owns channels [cc*8, cc*8+8).
// Lane-split coords + packed width-4 shuffle exchange; f32x2 accumulation.
// Ref view read from ORIGINAL f32 feats (exact, no transpose needed).
// ---------------------------------------------------------------------------
__global__ void __launch_bounds__(256, 4)
hammer_kernel(const float* __restrict__ feats,
              const float* __restrict__ depthv,
              float* __restrict__ outv,
              float* __restrict__ outm)
{
    __shared__ float s_rt[Bn*Vn*12];
    const int t = threadIdx.x;
    if (t < Bn*Vn*12) s_rt[t] = g_rt[t];
    __syncthreads();

    const int gid = blockIdx.x*256 + t;
    const int cc  = gid & 3;
    const int pg  = gid >> 2;          // 0..Bn*HWn-1
    const int b   = pg / HWn;
    const int pix = pg - b*HWn;
    const float xf = (float)(pix % Wn);
    const float yf = (float)(pix / Wn);

    // depth for all 4 planes up front
    float dep4[Dn];
    #pragma unroll
    for (int d = 0; d < Dn; d++)
        dep4[d] = __ldg(depthv + (b*Dn + d)*HWn + pix);

    // reference view from original f32 layout (exact), channels cc*8..cc*8+7
    unsigned long long rvs[4];
    {
        const float* rp = feats + ((size_t)(b*Vn)*Cn + cc*8)*HWn + pix;
        float f[8];
        #pragma unroll
        for (int j = 0; j < 8; j++) f[j] = __ldg(rp + j*HWn);
        #pragma unroll
        for (int k = 0; k < 4; k++) rvs[k] = pk2(f[2*k], f[2*k+1]);
    }

    // this lane's view (vi = cc): row dots + translation, hoisted
    const float* M = &s_rt[(b*Vn + cc + 1)*12];
    const float Ar = fmaf(M[0], xf, fmaf(M[1], yf, M[2]));
    const float Br = fmaf(M[3], xf, fmaf(M[4], yf, M[5]));
    const float Cr = fmaf(M[6], xf, fmaf(M[7], yf, M[8]));
    const float T9 = M[9], T10 = M[10], T11 = M[11];
    const int   vline_mine = (b*4 + cc)*HWn;  // pixel-line index into g_fT (<2^20)

    const unsigned long long C02 = pk2( 0.2f,  0.2f);
    const unsigned long long CN2 = pk2(-0.2f, -0.2f);

    unsigned vbits = 0;

    #pragma unroll 1
    for (int d = 0; d < Dn; d++) {
        const float dep = dep4[d];

        // ---- my view's warp params ----
        float pxv = fmaf(Ar, dep, T9);
        float pyv = fmaf(Br, dep, T10);
        float pzv = fmaf(Cr, dep, T11);
        float rz = __frcp_rn(pzv);
        float gx = pxv * rz;
        float gy = pyv * rz;

        float fx0 = floorf(gx), fy0 = floorf(gy);
        float ax = gx - fx0,    ay = gy - fy0;
        int x0 = (int)fx0, y0 = (int)fy0;
        int x1 = x0 + 1,   y1 = y0 + 1;
        float wx0 = (x0 >= 0 && x0 < Wn) ? (1.f - ax) : 0.f;
        float wx1 = (x1 >= 0 && x1 < Wn) ? ax : 0.f;
        float wy0 = (y0 >= 0 && y0 < Hn) ? (1.f - ay) : 0.f;
        float wy1 = (y1 >= 0 && y1 < Hn) ? ay : 0.f;

        if (((wx0 + wx1) * (wy0 + wy1)) != 0.f) vbits |= (1u << d);

        int pb = min(max(x0, 0), Wn - 2);
        float wxA = (x0 == pb)     ? wx0 : ((x1 == pb)     ? wx1 : 0.f);
        float wxB = (x1 == pb + 1) ? wx1 : ((x0 == pb + 1) ? wx0 : 0.f);
        int y0c = min(max(y0, 0), Hn - 1);
        int y1c = min(max(y1, 0), Hn - 1);

        __half2 wxh = __floats2half2_rn(wxA, wxB);
        __half2 wyh = __floats2half2_rn(wy0, wy1);
        unsigned wxu = *(unsigned*)&wxh;
        unsigned wyu = *(unsigned*)&wyh;
        // pack both row offsets: 20-bit pixel-line index + 1-bit (y1c-y0c)
        int pko = (vline_mine + y0c*Wn + pb) | ((y1c - y0c) << 20);

        unsigned long long s2[4], q2[4];
        #pragma unroll
        for (int k = 0; k < 4; k++) {
            s2[k] = rvs[k];
            q2[k] = mul2(rvs[k], rvs[k]);
        }

        #pragma unroll
        for (int vi = 0; vi < 4; vi++) {
            int pv       = __shfl_sync(0xffffffffu, pko, vi, 4);
            unsigned wxb = __shfl_sync(0xffffffffu, wxu, vi, 4);
            unsigned wyb = __shfl_sync(0xffffffffu, wyu, vi, 4);
            int l0 = pv & 0xFFFFF;
            int l1 = l0 + ((pv >> 20) ? Wn : 0);
            __half2 wxv = *(__half2*)&wxb;
            __half2 wyv = *(__half2*)&wyb;
            __half2 wxA2 = __half2half2(__low2half(wxv));
            __half2 wxB2 = __half2half2(__high2half(wxv));
            __half2 wy02 = __half2half2(__low2half(wyv));
            __half2 wy12 = __half2half2(__high2half(wyv));

            const __half2* r0 = g_fT + (size_t)l0*16 + cc*4;
            const __half2* r1 = g_fT + (size_t)l1*16 + cc*4;
            uint4 u00 = __ldg((const uint4*)r0);
            uint4 u01 = __ldg((const uint4*)(r0 + 16));
            uint4 u10 = __ldg((const uint4*)r1);
            uint4 u11 = __ldg((const uint4*)(r1 + 16));

            const __half2* h00 = (const __half2*)&u00;
            const __half2* h01 = (const __half2*)&u01;
            const __half2* h10 = (const __half2*)&u10;
            const __half2* h11 = (const __half2*)&u11;

            #pragma unroll
            for (int k = 0; k < 4; k++) {
                __half2 ra = __hfma2(wxB2, h01[k], __hmul2(wxA2, h00[k]));
                __half2 rb = __hfma2(wxB2, h11[k], __hmul2(wxA2, h10[k]));
                __half2 v2 = __hfma2(wy12, rb, __hmul2(wy02, ra));
                acc2(s2[k], q2[k], __half22float2(v2));
            }
        }

        const int ob = ((b*Cn + cc*8)*Dn + d)*HWn + pix;
        #pragma unroll
        for (int k = 0; k < 4; k++) {
            // var = q*0.2 - (s*0.2)^2 = fma(s*0.2, s*(-0.2), q*0.2)
            unsigned long long u  = mul2(s2[k], C02);
            unsigned long long un = mul2(s2[k], CN2);
            unsigned long long qc = mul2(q2[k], C02);
            float2 r = upk2(fma2(u, un, qc));
            outv[ob + (2*k)  *(Dn*HWn)] = r.x;
            outv[ob + (2*k+1)*(Dn*HWn)] = r.y;
        }
    }

    // mask: popcount own-view bits, sum across the 4 views of this pixel
    int ms = __popc(vbits);
    ms += __shfl_xor_sync(0xffffffffu, ms, 1, 4);
    ms += __shfl_xor_sync(0xffffffffu, ms, 2, 4);
    if (cc == 0) outm[b*HWn + pix] = (float)ms;
}

// ---------------------------------------------------------------------------
// Launch
// ---------------------------------------------------------------------------
extern "C" void kernel_launch(void* const* d_in, const int* in_sizes, int n_in,
                              void* d_out, int out_size)
{
    const float* feats  = (const float*)d_in[0];
    const float* proj   = (const float*)d_in[1];
    const float* depthv = (const float*)d_in[2];

    float* outv = (float*)d_out;
    float* outm = outv + VAR_ELEMS;

    transpose_kernel<<<dim3(HWn/64, Bn*4), 256>>>(feats, proj);
    hammer_kernel<<<(Bn*HWn*4)/256, 256>>>(feats, depthv, outv, outm);
}